// round 13
// baseline (speedup 1.0000x reference)
#include <cuda_runtime.h>

#define MAXN 50000
#define MAXE 1600000
#define RR 8

// Scratch: static device globals, referenced ONLY from device code.
__device__ __align__(16) float g_xw[(size_t)RR * MAXN * 64]; // [R][N][64] transformed feats
__device__ __align__(16) float g_h [(size_t)MAXN * 64];      // layer-1 output (pre-relu)
__device__ __align__(16) float g_wdup[221184];   // duplicated weights: L1 [9][128][64][2], L2 [9][64][64][2]
__device__ int g_cnt[MAXN * RR];       // (dst, relation) edge counts
__device__ int g_deg[MAXN];            // total in-degree per dst
__device__ int g_rowstart[MAXN];       // CSR row starts (block-local; add g_blocksum)
__device__ int g_fill[MAXN];           // fill cursors
__device__ int g_blocksum[512];        // scan partials (exclusive block offsets)
__device__ int g_eidx[MAXE];           // packed (src<<3)|rel, grouped by dst
__device__ int g_w64;                  // bit0: edge_type is int64, bit1: edge_index is int64

#define L2_DUP_OFF 147456              // 9*128*64*2 floats (layer-1 dup block)

__device__ __forceinline__ int clampi(int v, int lo, int hi) {
    return min(max(v, lo), hi);
}

__device__ __forceinline__ void load_edge(const void* ei, const void* et, int E,
                                          int N, int e, int& src, int& dst, int& r) {
    int w = g_w64;
    if (w & 2) {
        const long long* p = (const long long*)ei;
        src = (int)p[e];
        dst = (int)p[(size_t)E + e];
    } else {
        const int* p = (const int*)ei;
        src = p[e];
        dst = p[(size_t)E + e];
    }
    if (w & 1) r = (int)((const long long*)et)[e];
    else       r = ((const int*)et)[e];
    src = clampi(src, 0, N - 1);
    dst = clampi(dst, 0, N - 1);
    r &= 7;
}

__device__ __forceinline__ void fma2(unsigned long long& d, unsigned long long a,
                                     unsigned long long b) {
    asm("fma.rn.f32x2 %0, %1, %2, %0;" : "+l"(d) : "l"(a), "l"(b));
}
__device__ __forceinline__ float lo2(unsigned long long v) {
    return __uint_as_float((unsigned)(v & 0xffffffffull));
}
__device__ __forceinline__ float hi2(unsigned long long v) {
    return __uint_as_float((unsigned)(v >> 32));
}

// ------------------------------------------------- dtype probe + zero (merged)
__global__ void dz_kernel(const void* ei, const void* et, int E, int N,
                          int n_cnt, int n_fill) {
    int i = blockIdx.x * blockDim.x + threadIdx.x;
    if (i < n_cnt) g_cnt[i] = 0;
    if (i < n_fill) g_fill[i] = 0;
    if (blockIdx.x == 0) {
        __shared__ int bad_et, bad_ei;
        if (threadIdx.x == 0) { bad_et = 0; bad_ei = 0; }
        __syncthreads();
        int M = min(E, 1024);
        const long long* et64 = (const long long*)et;
        const long long* ei64 = (const long long*)ei;
        for (int j = threadIdx.x; j < M; j += blockDim.x) {
            long long v = et64[j];
            if (v < 0 || v >= RR) bad_et = 1;
            long long s = ei64[j];
            if (s < 0 || s >= N) bad_ei = 1;
        }
        __syncthreads();
        if (threadIdx.x == 0) g_w64 = (bad_et ? 0 : 1) | (bad_ei ? 0 : 2);
    }
}

// -------------------------------------------- weight duplication (both layers)
// g_wdup layer1: [(r*128 + k)*64 + c] as float2 (w, w);  r=8 is root.
// g_wdup layer2 at L2_DUP_OFF: [(r*64 + k)*64 + c] as float2.
__global__ void wdup_kernel(const float* __restrict__ W1r,
                            const float* __restrict__ W1o,
                            const float* __restrict__ W2r,
                            const float* __restrict__ W2o) {
    int idx = blockIdx.x * blockDim.x + threadIdx.x;
    const int L1 = 9 * 128 * 64;           // 73728
    const int L2 = 9 * 64 * 64;            // 36864
    if (idx < L1) {
        int r = idx / (128 * 64);
        int rem = idx % (128 * 64);        // k*64 + c
        float w = (r < 8) ? W1r[idx] : W1o[rem];
        *reinterpret_cast<float2*>(&g_wdup[(size_t)idx * 2]) = make_float2(w, w);
    } else if (idx < L1 + L2) {
        int j = idx - L1;
        int r = j / (64 * 64);
        int rem = j % (64 * 64);
        float w = (r < 8) ? W2r[j] : W2o[rem];
        *reinterpret_cast<float2*>(&g_wdup[L2_DUP_OFF + (size_t)j * 2]) =
            make_float2(w, w);
    }
}

// ---------------------------------------------------------------- CSR build
__global__ void count_kernel(const void* ei, const void* et, int E, int N) {
    int e = blockIdx.x * blockDim.x + threadIdx.x;
    if (e < E) {
        int src, dst, r;
        load_edge(ei, et, E, N, e, src, dst, r);
        atomicAdd(&g_cnt[dst * RR + r], 1);
    }
}

__global__ void scan1_kernel(int N) {
    __shared__ int s[512];
    int d = blockIdx.x * 512 + threadIdx.x;
    int deg = 0;
    if (d < N) {
        for (int r = 0; r < RR; r++) deg += g_cnt[d * RR + r];
    }
    s[threadIdx.x] = deg;
    __syncthreads();
    for (int off = 1; off < 512; off <<= 1) {
        int v = (threadIdx.x >= off) ? s[threadIdx.x - off] : 0;
        __syncthreads();
        s[threadIdx.x] += v;
        __syncthreads();
    }
    int incl = s[threadIdx.x];
    if (d < N) { g_rowstart[d] = incl - deg; g_deg[d] = deg; }
    if (threadIdx.x == 511) g_blocksum[blockIdx.x] = incl;
}

__global__ void scan2_kernel(int nb) {
    __shared__ int s[512];
    int v = (threadIdx.x < nb) ? g_blocksum[threadIdx.x] : 0;
    s[threadIdx.x] = v;
    __syncthreads();
    for (int off = 1; off < 512; off <<= 1) {
        int p = (threadIdx.x >= off) ? s[threadIdx.x - off] : 0;
        __syncthreads();
        s[threadIdx.x] += p;
        __syncthreads();
    }
    if (threadIdx.x < nb) g_blocksum[threadIdx.x] = s[threadIdx.x] - v; // exclusive
}

__global__ void fill_kernel(const void* ei, const void* et, int E, int N) {
    int e = blockIdx.x * blockDim.x + threadIdx.x;
    if (e < E) {
        int src, dst, r;
        load_edge(ei, et, E, N, e, src, dst, r);
        int base = g_rowstart[dst] + g_blocksum[dst >> 9];
        int pos  = base + atomicAdd(&g_fill[dst], 1);
        pos = clampi(pos, 0, E - 1);
        g_eidx[pos] = (src << 3) | r;
    }
}

// ---------------------------------------------------------------- GEMM (f32x2)
// g_xw[r] = X @ Wrel[r] (r=0..7), plus root: X @ Wroot + b into rootout.
// LAYER1: X = Xarg, rootout = g_h. LAYER2: X = relu(g_h), rootout = Oarg.
// R10 geometry (proven best occupancy): 128 threads -> 64 nodes x 64 cols,
// thread: 8 nodes x 4 cols. X tile transposed in smem (xs[k][node]).
// W read from g_wdup (pre-duplicated pairs) -> direct f32x2 operands, NO movs.
// Per k: 2 LDG.128 (dup W) + 2 LDS.128 (x) + 16 FFMA2  => ~84% FMA2 issue mix.
template <int K, int LAYER>
__global__ void __launch_bounds__(128)
gemm_kernel(const float* __restrict__ Xarg,
            const float* __restrict__ bias,
            float* __restrict__ Oarg, int N) {
    const float* X = (LAYER == 1) ? Xarg : g_h;
    float* rootout = (LAYER == 1) ? g_h : Oarg;
    const float* WD = g_wdup + ((LAYER == 1) ? 0 : L2_DUP_OFF);

    __shared__ float xs[K][72];   // [k][node], 72-float rows (16B-aligned, bank-safe)
    int n0 = blockIdx.x * 64;

    const int NV = 64 * (K / 4);
    for (int idx = threadIdx.x; idx < NV; idx += blockDim.x) {
        int row = idx & 63;
        int q   = idx >> 6;
        float4 v = make_float4(0.f, 0.f, 0.f, 0.f);
        if (n0 + row < N)
            v = reinterpret_cast<const float4*>(X)[(size_t)(n0 + row) * (K / 4) + q];
        if (LAYER == 2) {
            v.x = fmaxf(v.x, 0.f); v.y = fmaxf(v.y, 0.f);
            v.z = fmaxf(v.z, 0.f); v.w = fmaxf(v.w, 0.f);
        }
        xs[4 * q + 0][row] = v.x; xs[4 * q + 1][row] = v.y;
        xs[4 * q + 2][row] = v.z; xs[4 * q + 3][row] = v.w;
    }
    __syncthreads();

    int cg = threadIdx.x & 15;  // column group: cols [cg*4, cg*4+4)
    int i  = threadIdx.x >> 4;  // node group: nodes [i*8, i*8+8)

    for (int r = 0; r < 9; r++) {
        // dup-W row for (r, k) is 128 floats; this thread's 4 cols at +cg*8.
        const float* Wrow = WD + (size_t)r * K * 128 + cg * 8;
        unsigned long long acc[4][4];   // [col j][node-pair p]
#pragma unroll
        for (int j = 0; j < 4; j++)
#pragma unroll
            for (int p = 0; p < 4; p++) acc[j][p] = 0ull;

#pragma unroll 8
        for (int k = 0; k < K; k++) {
            const ulonglong2* lw =
                reinterpret_cast<const ulonglong2*>(Wrow + (size_t)k * 128);
            ulonglong2 l0 = lw[0], l1 = lw[1];
            unsigned long long w[4] = {l0.x, l0.y, l1.x, l1.y};
            const ulonglong2* xp =
                reinterpret_cast<const ulonglong2*>(&xs[k][i * 8]);
            ulonglong2 xa = xp[0], xb = xp[1];
            unsigned long long xpair[4] = {xa.x, xa.y, xb.x, xb.y};
#pragma unroll
            for (int j = 0; j < 4; j++)
#pragma unroll
                for (int p = 0; p < 4; p++)
                    fma2(acc[j][p], xpair[p], w[j]);
        }

#pragma unroll
        for (int n = 0; n < 8; n++) {
            int node = n0 + i * 8 + n;
            if (node < N) {
                int p = n >> 1;
                float c0 = (n & 1) ? hi2(acc[0][p]) : lo2(acc[0][p]);
                float c1 = (n & 1) ? hi2(acc[1][p]) : lo2(acc[1][p]);
                float c2 = (n & 1) ? hi2(acc[2][p]) : lo2(acc[2][p]);
                float c3 = (n & 1) ? hi2(acc[3][p]) : lo2(acc[3][p]);
                if (r < 8) {
                    *reinterpret_cast<float4*>(
                        g_xw + ((size_t)r * N + node) * 64 + cg * 4) =
                        make_float4(c0, c1, c2, c3);
                } else {
                    float4 b = reinterpret_cast<const float4*>(bias)[cg];
                    *reinterpret_cast<float4*>(
                        rootout + (size_t)node * 64 + cg * 4) =
                        make_float4(c0 + b.x, c1 + b.y, c2 + b.z, c3 + b.w);
                }
            }
        }
    }
}

// ---------------------------------------------------------------- Aggregation
// One WARP per dst node (no intra-warp divergence); lane handles 2 cols (float2).
// Unrolled x4: four independent 256B gathers in flight; two accumulator chains.
template <int LAYER>
__global__ void agg_kernel(float* __restrict__ Oarg, int N) {
    float* inout = (LAYER == 1) ? g_h : Oarg;

    int dst  = blockIdx.x * 8 + (threadIdx.x >> 5);
    int lane = threadIdx.x & 31;
    if (dst >= N) return;

    int start = g_rowstart[dst] + g_blocksum[dst >> 9];
    int dg    = g_deg[dst];

    float inv[RR];
#pragma unroll
    for (int r = 0; r < RR; r++) {
        int c = g_cnt[dst * RR + r];
        inv[r] = 1.0f / (float)(c > 0 ? c : 1);
    }

    const float* base = g_xw + (size_t)lane * 2;
    float2 accA = make_float2(0.f, 0.f);
    float2 accB = make_float2(0.f, 0.f);

    int i = 0;
    for (; i + 4 <= dg; i += 4) {
        int e0 = g_eidx[start + i];
        int e1 = g_eidx[start + i + 1];
        int e2 = g_eidx[start + i + 2];
        int e3 = g_eidx[start + i + 3];
        float2 v0 = *reinterpret_cast<const float2*>(
            base + ((size_t)(e0 & 7) * N + (e0 >> 3)) * 64);
        float2 v1 = *reinterpret_cast<const float2*>(
            base + ((size_t)(e1 & 7) * N + (e1 >> 3)) * 64);
        float2 v2 = *reinterpret_cast<const float2*>(
            base + ((size_t)(e2 & 7) * N + (e2 >> 3)) * 64);
        float2 v3 = *reinterpret_cast<const float2*>(
            base + ((size_t)(e3 & 7) * N + (e3 >> 3)) * 64);
        float s0 = inv[e0 & 7], s1 = inv[e1 & 7], s2 = inv[e2 & 7], s3 = inv[e3 & 7];
        accA.x = fmaf(v0.x, s0, accA.x); accA.y = fmaf(v0.y, s0, accA.y);
        accB.x = fmaf(v1.x, s1, accB.x); accB.y = fmaf(v1.y, s1, accB.y);
        accA.x = fmaf(v2.x, s2, accA.x); accA.y = fmaf(v2.y, s2, accA.y);
        accB.x = fmaf(v3.x, s3, accB.x); accB.y = fmaf(v3.y, s3, accB.y);
    }
    for (; i < dg; i++) {
        int e0 = g_eidx[start + i];
        float s0 = inv[e0 & 7];
        float2 v0 = *reinterpret_cast<const float2*>(
            base + ((size_t)(e0 & 7) * N + (e0 >> 3)) * 64);
        accA.x = fmaf(v0.x, s0, accA.x); accA.y = fmaf(v0.y, s0, accA.y);
    }

    float2* o = reinterpret_cast<float2*>(inout + (size_t)dst * 64 + lane * 2);
    float2 old = *o;
    old.x += accA.x + accB.x;
    old.y += accA.y + accB.y;
    *o = old;
}

// ---------------------------------------------------------------- launch
extern "C" void kernel_launch(void* const* d_in, const int* in_sizes, int n_in,
                              void* d_out, int out_size) {
    const float* x   = (const float*)d_in[0];
    const void*  ei  = d_in[1];
    const void*  et  = d_in[2];
    const float* W1r = (const float*)d_in[3];
    const float* W1o = (const float*)d_in[4];
    const float* b1  = (const float*)d_in[5];
    const float* W2r = (const float*)d_in[6];
    const float* W2o = (const float*)d_in[7];
    const float* b2  = (const float*)d_in[8];
    float* out = (float*)d_out;

    int N = in_sizes[0] / 128;
    int E = in_sizes[2];

    int nb = (N + 511) / 512;
    int gb = (N + 63) / 64;
    int ab = (N + 7) / 8;
    int wb = (9 * 128 * 64 + 9 * 64 * 64 + 255) / 256;

    // gemm1 kept at launch index 3 (ncu capture window). Deps preserved on stream 0.
    dz_kernel<<<(N * RR + 255) / 256, 256>>>(ei, et, E, N, N * RR, N);      // 0
    count_kernel<<<(E + 255) / 256, 256>>>(ei, et, E, N);                    // 1
    wdup_kernel<<<wb, 256>>>(W1r, W1o, W2r, W2o);                            // 2
    gemm_kernel<128, 1><<<gb, 128>>>(x, b1, nullptr, N);                     // 3
    scan1_kernel<<<nb, 512>>>(N);                                            // 4
    scan2_kernel<<<1, 512>>>(nb);                                            // 5
    fill_kernel<<<(E + 255) / 256, 256>>>(ei, et, E, N);                     // 6
    agg_kernel<1><<<ab, 256>>>(nullptr, N);                                  // 7
    gemm_kernel<64, 2><<<gb, 128>>>(nullptr, b2, out, N);                    // 8
    agg_kernel<2><<<ab, 256>>>(out, N);                                      // 9
}

// round 14
// speedup vs baseline: 1.9045x; 1.9045x over previous
#include <cuda_runtime.h>

#define MAXN 50000
#define MAXE 1600000
#define RR 8

// Scratch: static device globals, referenced ONLY from device code.
__device__ __align__(16) float g_xw[(size_t)RR * MAXN * 64]; // [R][N][64] transformed feats
__device__ __align__(16) float g_h [(size_t)MAXN * 64];      // layer-1 output (pre-relu)
__device__ int g_cnt[MAXN * RR];       // (dst, relation) edge counts
__device__ int g_deg[MAXN];            // total in-degree per dst
__device__ int g_rowstart[MAXN];       // CSR row starts (block-local; add g_blocksum)
__device__ int g_fill[MAXN];           // fill cursors
__device__ int g_blocksum[512];        // scan partials (exclusive block offsets)
__device__ int g_eidx[MAXE];           // packed (src<<3)|rel, grouped by dst
__device__ int g_w64;                  // bit0: edge_type is int64, bit1: edge_index is int64

__device__ __forceinline__ int clampi(int v, int lo, int hi) {
    return min(max(v, lo), hi);
}

__device__ __forceinline__ void load_edge(const void* ei, const void* et, int E,
                                          int N, int e, int& src, int& dst, int& r) {
    int w = g_w64;
    if (w & 2) {
        const long long* p = (const long long*)ei;
        src = (int)p[e];
        dst = (int)p[(size_t)E + e];
    } else {
        const int* p = (const int*)ei;
        src = p[e];
        dst = p[(size_t)E + e];
    }
    if (w & 1) r = (int)((const long long*)et)[e];
    else       r = ((const int*)et)[e];
    src = clampi(src, 0, N - 1);
    dst = clampi(dst, 0, N - 1);
    r &= 7;
}

__device__ __forceinline__ unsigned long long bcast2(float x) {
    unsigned long long r;
    asm("mov.b64 %0, {%1, %1};" : "=l"(r) : "r"(__float_as_uint(x)));
    return r;
}
__device__ __forceinline__ void fma2(unsigned long long& d, unsigned long long a,
                                     unsigned long long b) {
    asm("fma.rn.f32x2 %0, %1, %2, %0;" : "+l"(d) : "l"(a), "l"(b));
}
__device__ __forceinline__ float lo2(unsigned long long v) {
    return __uint_as_float((unsigned)(v & 0xffffffffull));
}
__device__ __forceinline__ float hi2(unsigned long long v) {
    return __uint_as_float((unsigned)(v >> 32));
}

// ------------------------------------------------- dtype probe + zero (merged)
__global__ void dz_kernel(const void* ei, const void* et, int E, int N,
                          int n_cnt, int n_fill) {
    int i = blockIdx.x * blockDim.x + threadIdx.x;
    if (i < n_cnt) g_cnt[i] = 0;
    if (i < n_fill) g_fill[i] = 0;
    if (blockIdx.x == 0) {
        __shared__ int bad_et, bad_ei;
        if (threadIdx.x == 0) { bad_et = 0; bad_ei = 0; }
        __syncthreads();
        int M = min(E, 1024);
        const long long* et64 = (const long long*)et;
        const long long* ei64 = (const long long*)ei;
        for (int j = threadIdx.x; j < M; j += blockDim.x) {
            long long v = et64[j];
            if (v < 0 || v >= RR) bad_et = 1;
            long long s = ei64[j];
            if (s < 0 || s >= N) bad_ei = 1;
        }
        __syncthreads();
        if (threadIdx.x == 0) g_w64 = (bad_et ? 0 : 1) | (bad_ei ? 0 : 2);
    }
}

// ---------------------------------------------------------------- CSR build
__global__ void count_kernel(const void* ei, const void* et, int E, int N) {
    int e = blockIdx.x * blockDim.x + threadIdx.x;
    if (e < E) {
        int src, dst, r;
        load_edge(ei, et, E, N, e, src, dst, r);
        atomicAdd(&g_cnt[dst * RR + r], 1);
    }
}

__global__ void scan1_kernel(int N) {
    __shared__ int s[512];
    int d = blockIdx.x * 512 + threadIdx.x;
    int deg = 0;
    if (d < N) {
        for (int r = 0; r < RR; r++) deg += g_cnt[d * RR + r];
    }
    s[threadIdx.x] = deg;
    __syncthreads();
    for (int off = 1; off < 512; off <<= 1) {
        int v = (threadIdx.x >= off) ? s[threadIdx.x - off] : 0;
        __syncthreads();
        s[threadIdx.x] += v;
        __syncthreads();
    }
    int incl = s[threadIdx.x];
    if (d < N) { g_rowstart[d] = incl - deg; g_deg[d] = deg; }
    if (threadIdx.x == 511) g_blocksum[blockIdx.x] = incl;
}

__global__ void scan2_kernel(int nb) {
    __shared__ int s[512];
    int v = (threadIdx.x < nb) ? g_blocksum[threadIdx.x] : 0;
    s[threadIdx.x] = v;
    __syncthreads();
    for (int off = 1; off < 512; off <<= 1) {
        int p = (threadIdx.x >= off) ? s[threadIdx.x - off] : 0;
        __syncthreads();
        s[threadIdx.x] += p;
        __syncthreads();
    }
    if (threadIdx.x < nb) g_blocksum[threadIdx.x] = s[threadIdx.x] - v; // exclusive
}

__global__ void fill_kernel(const void* ei, const void* et, int E, int N) {
    int e = blockIdx.x * blockDim.x + threadIdx.x;
    if (e < E) {
        int src, dst, r;
        load_edge(ei, et, E, N, e, src, dst, r);
        int base = g_rowstart[dst] + g_blocksum[dst >> 9];
        int pos  = base + atomicAdd(&g_fill[dst], 1);
        pos = clampi(pos, 0, E - 1);
        g_eidx[pos] = (src << 3) | r;
    }
}

// ---------------------------------------------------------------- GEMM (f32x2)
// g_xw[r] = X @ Wrel[r] (r=0..7), plus root: X @ Wroot + b into rootout.
// LAYER1: X = Xarg, rootout = g_h. LAYER2: X = relu(g_h), rootout = Oarg.
// OCCUPANCY-FIRST tile: 128 threads -> 32 nodes x 64 cols; thread: 4 nodes x 4 cols.
// acc = 8 u64 (16 regs) -> ~45 regs total -> ~5-6 blocks/SM (~60% occ, was 32%).
// X tile transposed in smem xs[k][node] (pitch 36 floats = 18.5 KB for K=128).
// Per k: 1 LDG.128 (W, warp-broadcast 16 lines) + 1 LDS.128 (x, 2-line broadcast)
//        + 4 bcast + 8 FFMA2.
template <int K, int LAYER>
__global__ void __launch_bounds__(128)
gemm_kernel(const float* __restrict__ Xarg,
            const float* __restrict__ Wrel,
            const float* __restrict__ Wroot,
            const float* __restrict__ bias,
            float* __restrict__ Oarg, int N) {
    const float* X = (LAYER == 1) ? Xarg : g_h;
    float* rootout = (LAYER == 1) ? g_h : Oarg;

    __shared__ float xs[K][36];   // [k][node], pitch 36 (144B rows, 16B-aligned)
    int n0 = blockIdx.x * 32;

    // Load + transpose the 32-node X tile.
    const int NV = 32 * (K / 4);
    for (int idx = threadIdx.x; idx < NV; idx += blockDim.x) {
        int row = idx & 31;
        int q   = idx >> 5;
        float4 v = make_float4(0.f, 0.f, 0.f, 0.f);
        if (n0 + row < N)
            v = reinterpret_cast<const float4*>(X)[(size_t)(n0 + row) * (K / 4) + q];
        if (LAYER == 2) {
            v.x = fmaxf(v.x, 0.f); v.y = fmaxf(v.y, 0.f);
            v.z = fmaxf(v.z, 0.f); v.w = fmaxf(v.w, 0.f);
        }
        xs[4 * q + 0][row] = v.x; xs[4 * q + 1][row] = v.y;
        xs[4 * q + 2][row] = v.z; xs[4 * q + 3][row] = v.w;
    }
    __syncthreads();

    int cg = threadIdx.x & 15;  // column group: cols [cg*4, cg*4+4)
    int i  = threadIdx.x >> 4;  // node group: nodes [i*4, i*4+4)

    for (int r = 0; r < 9; r++) {
        const float* W = (r < 8) ? (Wrel + (size_t)r * K * 64) : Wroot;
        unsigned long long acc[4][2];   // [col j][node-pair p]
#pragma unroll
        for (int j = 0; j < 4; j++) { acc[j][0] = 0ull; acc[j][1] = 0ull; }

#pragma unroll 8
        for (int k = 0; k < K; k++) {
            float4 wv = *reinterpret_cast<const float4*>(W + (size_t)k * 64 + cg * 4);
            unsigned long long wb[4] = {bcast2(wv.x), bcast2(wv.y),
                                        bcast2(wv.z), bcast2(wv.w)};
            const ulonglong2* xp =
                reinterpret_cast<const ulonglong2*>(&xs[k][i * 4]);
            ulonglong2 xa = xp[0];
#pragma unroll
            for (int j = 0; j < 4; j++) {
                fma2(acc[j][0], xa.x, wb[j]);
                fma2(acc[j][1], xa.y, wb[j]);
            }
        }

#pragma unroll
        for (int n = 0; n < 4; n++) {
            int node = n0 + i * 4 + n;
            if (node < N) {
                int p = n >> 1;
                float c0 = (n & 1) ? hi2(acc[0][p]) : lo2(acc[0][p]);
                float c1 = (n & 1) ? hi2(acc[1][p]) : lo2(acc[1][p]);
                float c2 = (n & 1) ? hi2(acc[2][p]) : lo2(acc[2][p]);
                float c3 = (n & 1) ? hi2(acc[3][p]) : lo2(acc[3][p]);
                if (r < 8) {
                    *reinterpret_cast<float4*>(
                        g_xw + ((size_t)r * N + node) * 64 + cg * 4) =
                        make_float4(c0, c1, c2, c3);
                } else {
                    float4 b = reinterpret_cast<const float4*>(bias)[cg];
                    *reinterpret_cast<float4*>(
                        rootout + (size_t)node * 64 + cg * 4) =
                        make_float4(c0 + b.x, c1 + b.y, c2 + b.z, c3 + b.w);
                }
            }
        }
    }
}

// ---------------------------------------------------------------- Aggregation
// One WARP per dst node (no intra-warp divergence); lane handles 2 cols (float2).
// Unrolled x4: four independent 256B gathers in flight; two accumulator chains.
template <int LAYER>
__global__ void agg_kernel(float* __restrict__ Oarg, int N) {
    float* inout = (LAYER == 1) ? g_h : Oarg;

    int dst  = blockIdx.x * 8 + (threadIdx.x >> 5);
    int lane = threadIdx.x & 31;
    if (dst >= N) return;

    int start = g_rowstart[dst] + g_blocksum[dst >> 9];
    int dg    = g_deg[dst];

    float inv[RR];
#pragma unroll
    for (int r = 0; r < RR; r++) {
        int c = g_cnt[dst * RR + r];
        inv[r] = 1.0f / (float)(c > 0 ? c : 1);
    }

    const float* base = g_xw + (size_t)lane * 2;
    float2 accA = make_float2(0.f, 0.f);
    float2 accB = make_float2(0.f, 0.f);

    int i = 0;
    for (; i + 4 <= dg; i += 4) {
        int e0 = g_eidx[start + i];
        int e1 = g_eidx[start + i + 1];
        int e2 = g_eidx[start + i + 2];
        int e3 = g_eidx[start + i + 3];
        float2 v0 = *reinterpret_cast<const float2*>(
            base + ((size_t)(e0 & 7) * N + (e0 >> 3)) * 64);
        float2 v1 = *reinterpret_cast<const float2*>(
            base + ((size_t)(e1 & 7) * N + (e1 >> 3)) * 64);
        float2 v2 = *reinterpret_cast<const float2*>(
            base + ((size_t)(e2 & 7) * N + (e2 >> 3)) * 64);
        float2 v3 = *reinterpret_cast<const float2*>(
            base + ((size_t)(e3 & 7) * N + (e3 >> 3)) * 64);
        float s0 = inv[e0 & 7], s1 = inv[e1 & 7], s2 = inv[e2 & 7], s3 = inv[e3 & 7];
        accA.x = fmaf(v0.x, s0, accA.x); accA.y = fmaf(v0.y, s0, accA.y);
        accB.x = fmaf(v1.x, s1, accB.x); accB.y = fmaf(v1.y, s1, accB.y);
        accA.x = fmaf(v2.x, s2, accA.x); accA.y = fmaf(v2.y, s2, accA.y);
        accB.x = fmaf(v3.x, s3, accB.x); accB.y = fmaf(v3.y, s3, accB.y);
    }
    for (; i < dg; i++) {
        int e0 = g_eidx[start + i];
        float s0 = inv[e0 & 7];
        float2 v0 = *reinterpret_cast<const float2*>(
            base + ((size_t)(e0 & 7) * N + (e0 >> 3)) * 64);
        accA.x = fmaf(v0.x, s0, accA.x); accA.y = fmaf(v0.y, s0, accA.y);
    }

    float2* o = reinterpret_cast<float2*>(inout + (size_t)dst * 64 + lane * 2);
    float2 old = *o;
    old.x += accA.x + accB.x;
    old.y += accA.y + accB.y;
    *o = old;
}

// ---------------------------------------------------------------- launch
extern "C" void kernel_launch(void* const* d_in, const int* in_sizes, int n_in,
                              void* d_out, int out_size) {
    const float* x   = (const float*)d_in[0];
    const void*  ei  = d_in[1];
    const void*  et  = d_in[2];
    const float* W1r = (const float*)d_in[3];
    const float* W1o = (const float*)d_in[4];
    const float* b1  = (const float*)d_in[5];
    const float* W2r = (const float*)d_in[6];
    const float* W2o = (const float*)d_in[7];
    const float* b2  = (const float*)d_in[8];
    float* out = (float*)d_out;

    int N = in_sizes[0] / 128;
    int E = in_sizes[2];

    int nb = (N + 511) / 512;
    int gb = (N + 31) / 32;
    int ab = (N + 7) / 8;

    // gemm1 kept at launch index 3 (ncu capture window). Deps preserved on stream 0.
    dz_kernel<<<(N * RR + 255) / 256, 256>>>(ei, et, E, N, N * RR, N);      // 0
    count_kernel<<<(E + 255) / 256, 256>>>(ei, et, E, N);                    // 1
    scan1_kernel<<<nb, 512>>>(N);                                            // 2
    gemm_kernel<128, 1><<<gb, 128>>>(x, W1r, W1o, b1, nullptr, N);           // 3
    scan2_kernel<<<1, 512>>>(nb);                                            // 4
    fill_kernel<<<(E + 255) / 256, 256>>>(ei, et, E, N);                     // 5
    agg_kernel<1><<<ab, 256>>>(nullptr, N);                                  // 6
    gemm_kernel<64, 2><<<gb, 128>>>(nullptr, W2r, W2o, b2, out, N);          // 7
    agg_kernel<2><<<ab, 256>>>(out, N);                                      // 8
}

// round 15
// speedup vs baseline: 2.5638x; 1.3462x over previous
#include <cuda_runtime.h>

#define MAXN 50000
#define MAXE 1600000
#define RR 8

// Scratch: static device globals, referenced ONLY from device code.
__device__ __align__(16) float g_xw[(size_t)RR * MAXN * 64]; // [R][N][64] transformed feats
__device__ __align__(16) float g_h [(size_t)MAXN * 64];      // layer-1 output (pre-relu)
__device__ int g_cnt[MAXN * RR];       // (dst, relation) edge counts
__device__ int g_deg[MAXN];            // total in-degree per dst
__device__ int g_rowstart[MAXN];       // CSR row starts (block-local; add g_blocksum)
__device__ int g_fill[MAXN];           // fill cursors
__device__ int g_blocksum[512];        // scan partials (exclusive block offsets)
__device__ int g_eidx[MAXE];           // packed (src<<3)|rel, grouped by dst
__device__ int g_w64;                  // bit0: edge_type is int64, bit1: edge_index is int64

__device__ __forceinline__ int clampi(int v, int lo, int hi) {
    return min(max(v, lo), hi);
}

__device__ __forceinline__ void load_edge(const void* ei, const void* et, int E,
                                          int N, int e, int& src, int& dst, int& r) {
    int w = g_w64;
    if (w & 2) {
        const long long* p = (const long long*)ei;
        src = (int)p[e];
        dst = (int)p[(size_t)E + e];
    } else {
        const int* p = (const int*)ei;
        src = p[e];
        dst = p[(size_t)E + e];
    }
    if (w & 1) r = (int)((const long long*)et)[e];
    else       r = ((const int*)et)[e];
    src = clampi(src, 0, N - 1);
    dst = clampi(dst, 0, N - 1);
    r &= 7;
}

__device__ __forceinline__ unsigned long long bcast2(float x) {
    unsigned long long r;
    asm("mov.b64 %0, {%1, %1};" : "=l"(r) : "r"(__float_as_uint(x)));
    return r;
}
__device__ __forceinline__ void fma2(unsigned long long& d, unsigned long long a,
                                     unsigned long long b) {
    asm("fma.rn.f32x2 %0, %1, %2, %0;" : "+l"(d) : "l"(a), "l"(b));
}
__device__ __forceinline__ float lo2(unsigned long long v) {
    return __uint_as_float((unsigned)(v & 0xffffffffull));
}
__device__ __forceinline__ float hi2(unsigned long long v) {
    return __uint_as_float((unsigned)(v >> 32));
}

// ------------------------------------------------- dtype probe + zero (merged)
__global__ void dz_kernel(const void* ei, const void* et, int E, int N,
                          int n_cnt, int n_fill) {
    int i = blockIdx.x * blockDim.x + threadIdx.x;
    if (i < n_cnt) g_cnt[i] = 0;
    if (i < n_fill) g_fill[i] = 0;
    if (blockIdx.x == 0) {
        __shared__ int bad_et, bad_ei;
        if (threadIdx.x == 0) { bad_et = 0; bad_ei = 0; }
        __syncthreads();
        int M = min(E, 1024);
        const long long* et64 = (const long long*)et;
        const long long* ei64 = (const long long*)ei;
        for (int j = threadIdx.x; j < M; j += blockDim.x) {
            long long v = et64[j];
            if (v < 0 || v >= RR) bad_et = 1;
            long long s = ei64[j];
            if (s < 0 || s >= N) bad_ei = 1;
        }
        __syncthreads();
        if (threadIdx.x == 0) g_w64 = (bad_et ? 0 : 1) | (bad_ei ? 0 : 2);
    }
}

// ---------------------------------------------------------------- CSR build
__global__ void count_kernel(const void* ei, const void* et, int E, int N) {
    int e = blockIdx.x * blockDim.x + threadIdx.x;
    if (e < E) {
        int src, dst, r;
        load_edge(ei, et, E, N, e, src, dst, r);
        atomicAdd(&g_cnt[dst * RR + r], 1);
    }
}

__global__ void scan1_kernel(int N) {
    __shared__ int s[512];
    int d = blockIdx.x * 512 + threadIdx.x;
    int deg = 0;
    if (d < N) {
        for (int r = 0; r < RR; r++) deg += g_cnt[d * RR + r];
    }
    s[threadIdx.x] = deg;
    __syncthreads();
    for (int off = 1; off < 512; off <<= 1) {
        int v = (threadIdx.x >= off) ? s[threadIdx.x - off] : 0;
        __syncthreads();
        s[threadIdx.x] += v;
        __syncthreads();
    }
    int incl = s[threadIdx.x];
    if (d < N) { g_rowstart[d] = incl - deg; g_deg[d] = deg; }
    if (threadIdx.x == 511) g_blocksum[blockIdx.x] = incl;
}

__global__ void scan2_kernel(int nb) {
    __shared__ int s[512];
    int v = (threadIdx.x < nb) ? g_blocksum[threadIdx.x] : 0;
    s[threadIdx.x] = v;
    __syncthreads();
    for (int off = 1; off < 512; off <<= 1) {
        int p = (threadIdx.x >= off) ? s[threadIdx.x - off] : 0;
        __syncthreads();
        s[threadIdx.x] += p;
        __syncthreads();
    }
    if (threadIdx.x < nb) g_blocksum[threadIdx.x] = s[threadIdx.x] - v; // exclusive
}

__global__ void fill_kernel(const void* ei, const void* et, int E, int N) {
    int e = blockIdx.x * blockDim.x + threadIdx.x;
    if (e < E) {
        int src, dst, r;
        load_edge(ei, et, E, N, e, src, dst, r);
        int base = g_rowstart[dst] + g_blocksum[dst >> 9];
        int pos  = base + atomicAdd(&g_fill[dst], 1);
        pos = clampi(pos, 0, E - 1);
        g_eidx[pos] = (src << 3) | r;
    }
}

// ---------------------------------------------------------------- GEMM (f32x2)
// g_xw[r] = X @ Wrel[r] (r=0..7), plus root: X @ Wroot + b into rootout.
// LAYER1: X = Xarg, rootout = g_h. LAYER2: X = relu(g_h), rootout = Oarg.
// 128 threads -> 32 nodes x 64 cols; thread: 4 nodes x 4 cols (R14 mapping).
// NO GMEM IN THE INNER LOOP: W is staged through a double-buffered smem
// pipeline (32-k chunks, prefetched into registers one chunk ahead), X is in
// transposed smem. Inner loop = 2 LDS.128 + 4 movs + 8 FFMA2 per k.
template <int K, int LAYER>
__global__ void __launch_bounds__(128)
gemm_kernel(const float* __restrict__ Xarg,
            const float* __restrict__ Wrel,
            const float* __restrict__ Wroot,
            const float* __restrict__ bias,
            float* __restrict__ Oarg, int N) {
    const float* X = (LAYER == 1) ? Xarg : g_h;
    float* rootout = (LAYER == 1) ? g_h : Oarg;

    const int KC  = 32;            // k-chunk
    const int CPR = K / KC;        // chunks per relation
    const int NCHUNK = 9 * CPR;

    __shared__ float xs[K][36];        // transposed X tile [k][node], pitch 36
    __shared__ float ws[2][KC * 64];   // W double buffer

    int n0 = blockIdx.x * 32;
    int tid = threadIdx.x;

    // Load + transpose the 32-node X tile.
    const int NV = 32 * (K / 4);
    for (int idx = tid; idx < NV; idx += blockDim.x) {
        int row = idx & 31;
        int q   = idx >> 5;
        float4 v = make_float4(0.f, 0.f, 0.f, 0.f);
        if (n0 + row < N)
            v = reinterpret_cast<const float4*>(X)[(size_t)(n0 + row) * (K / 4) + q];
        if (LAYER == 2) {
            v.x = fmaxf(v.x, 0.f); v.y = fmaxf(v.y, 0.f);
            v.z = fmaxf(v.z, 0.f); v.w = fmaxf(v.w, 0.f);
        }
        xs[4 * q + 0][row] = v.x; xs[4 * q + 1][row] = v.y;
        xs[4 * q + 2][row] = v.z; xs[4 * q + 3][row] = v.w;
    }

    // Preload W chunk 0 (relation 0, k 0..31): 512 float4, 4 per thread.
    {
        const float4* Wp = reinterpret_cast<const float4*>(Wrel);
#pragma unroll
        for (int q = 0; q < 4; q++)
            reinterpret_cast<float4*>(ws[0])[q * 128 + tid] = Wp[q * 128 + tid];
    }
    __syncthreads();

    int cg = tid & 15;  // column group: cols [cg*4, cg*4+4)
    int i  = tid >> 4;  // node group: nodes [i*4, i*4+4)

    unsigned long long acc[4][2];   // [col j][node-pair p]
#pragma unroll
    for (int j = 0; j < 4; j++) { acc[j][0] = 0ull; acc[j][1] = 0ull; }

    int cur = 0;
    for (int c = 0; c < NCHUNK; c++) {
        int r  = c / CPR;
        int kc = c % CPR;

        // Prefetch next chunk into registers (coalesced LDG.128, MLP=4).
        float4 pf0, pf1, pf2, pf3;
        bool havepf = (c + 1 < NCHUNK);
        if (havepf) {
            int nr  = (c + 1) / CPR;
            int nkc = (c + 1) % CPR;
            const float* Wn = (nr < 8) ? (Wrel + (size_t)nr * K * 64) : Wroot;
            const float4* Wp =
                reinterpret_cast<const float4*>(Wn + (size_t)nkc * KC * 64);
            pf0 = Wp[0 * 128 + tid];
            pf1 = Wp[1 * 128 + tid];
            pf2 = Wp[2 * 128 + tid];
            pf3 = Wp[3 * 128 + tid];
        }

        // Compute this chunk from smem only.
        const float* wbuf = ws[cur];
#pragma unroll 8
        for (int k = 0; k < KC; k++) {
            float4 wv = *reinterpret_cast<const float4*>(wbuf + k * 64 + cg * 4);
            unsigned long long wb[4] = {bcast2(wv.x), bcast2(wv.y),
                                        bcast2(wv.z), bcast2(wv.w)};
            const ulonglong2* xp =
                reinterpret_cast<const ulonglong2*>(&xs[kc * KC + k][i * 4]);
            ulonglong2 xa = xp[0];
#pragma unroll
            for (int j = 0; j < 4; j++) {
                fma2(acc[j][0], xa.x, wb[j]);
                fma2(acc[j][1], xa.y, wb[j]);
            }
        }

        // Epilogue at the last chunk of each relation.
        if (kc == CPR - 1) {
#pragma unroll
            for (int n = 0; n < 4; n++) {
                int node = n0 + i * 4 + n;
                if (node < N) {
                    int p = n >> 1;
                    float c0 = (n & 1) ? hi2(acc[0][p]) : lo2(acc[0][p]);
                    float c1 = (n & 1) ? hi2(acc[1][p]) : lo2(acc[1][p]);
                    float c2 = (n & 1) ? hi2(acc[2][p]) : lo2(acc[2][p]);
                    float c3 = (n & 1) ? hi2(acc[3][p]) : lo2(acc[3][p]);
                    if (r < 8) {
                        *reinterpret_cast<float4*>(
                            g_xw + ((size_t)r * N + node) * 64 + cg * 4) =
                            make_float4(c0, c1, c2, c3);
                    } else {
                        float4 b = reinterpret_cast<const float4*>(bias)[cg];
                        *reinterpret_cast<float4*>(
                            rootout + (size_t)node * 64 + cg * 4) =
                            make_float4(c0 + b.x, c1 + b.y, c2 + b.z, c3 + b.w);
                    }
                }
            }
#pragma unroll
            for (int j = 0; j < 4; j++) { acc[j][0] = 0ull; acc[j][1] = 0ull; }
        }

        // Store prefetched chunk into the other buffer; single barrier per chunk.
        if (havepf) {
            float4* wd = reinterpret_cast<float4*>(ws[cur ^ 1]);
            wd[0 * 128 + tid] = pf0;
            wd[1 * 128 + tid] = pf1;
            wd[2 * 128 + tid] = pf2;
            wd[3 * 128 + tid] = pf3;
        }
        __syncthreads();
        cur ^= 1;
    }
}

// ---------------------------------------------------------------- Aggregation
// One WARP per dst node (no intra-warp divergence); lane handles 2 cols (float2).
// Unrolled x4: four independent 256B gathers in flight; two accumulator chains.
template <int LAYER>
__global__ void agg_kernel(float* __restrict__ Oarg, int N) {
    float* inout = (LAYER == 1) ? g_h : Oarg;

    int dst  = blockIdx.x * 8 + (threadIdx.x >> 5);
    int lane = threadIdx.x & 31;
    if (dst >= N) return;

    int start = g_rowstart[dst] + g_blocksum[dst >> 9];
    int dg    = g_deg[dst];

    float inv[RR];
#pragma unroll
    for (int r = 0; r < RR; r++) {
        int c = g_cnt[dst * RR + r];
        inv[r] = 1.0f / (float)(c > 0 ? c : 1);
    }

    const float* base = g_xw + (size_t)lane * 2;
    float2 accA = make_float2(0.f, 0.f);
    float2 accB = make_float2(0.f, 0.f);

    int i = 0;
    for (; i + 4 <= dg; i += 4) {
        int e0 = g_eidx[start + i];
        int e1 = g_eidx[start + i + 1];
        int e2 = g_eidx[start + i + 2];
        int e3 = g_eidx[start + i + 3];
        float2 v0 = *reinterpret_cast<const float2*>(
            base + ((size_t)(e0 & 7) * N + (e0 >> 3)) * 64);
        float2 v1 = *reinterpret_cast<const float2*>(
            base + ((size_t)(e1 & 7) * N + (e1 >> 3)) * 64);
        float2 v2 = *reinterpret_cast<const float2*>(
            base + ((size_t)(e2 & 7) * N + (e2 >> 3)) * 64);
        float2 v3 = *reinterpret_cast<const float2*>(
            base + ((size_t)(e3 & 7) * N + (e3 >> 3)) * 64);
        float s0 = inv[e0 & 7], s1 = inv[e1 & 7], s2 = inv[e2 & 7], s3 = inv[e3 & 7];
        accA.x = fmaf(v0.x, s0, accA.x); accA.y = fmaf(v0.y, s0, accA.y);
        accB.x = fmaf(v1.x, s1, accB.x); accB.y = fmaf(v1.y, s1, accB.y);
        accA.x = fmaf(v2.x, s2, accA.x); accA.y = fmaf(v2.y, s2, accA.y);
        accB.x = fmaf(v3.x, s3, accB.x); accB.y = fmaf(v3.y, s3, accB.y);
    }
    for (; i < dg; i++) {
        int e0 = g_eidx[start + i];
        float s0 = inv[e0 & 7];
        float2 v0 = *reinterpret_cast<const float2*>(
            base + ((size_t)(e0 & 7) * N + (e0 >> 3)) * 64);
        accA.x = fmaf(v0.x, s0, accA.x); accA.y = fmaf(v0.y, s0, accA.y);
    }

    float2* o = reinterpret_cast<float2*>(inout + (size_t)dst * 64 + lane * 2);
    float2 old = *o;
    old.x += accA.x + accB.x;
    old.y += accA.y + accB.y;
    *o = old;
}

// ---------------------------------------------------------------- launch
extern "C" void kernel_launch(void* const* d_in, const int* in_sizes, int n_in,
                              void* d_out, int out_size) {
    const float* x   = (const float*)d_in[0];
    const void*  ei  = d_in[1];
    const void*  et  = d_in[2];
    const float* W1r = (const float*)d_in[3];
    const float* W1o = (const float*)d_in[4];
    const float* b1  = (const float*)d_in[5];
    const float* W2r = (const float*)d_in[6];
    const float* W2o = (const float*)d_in[7];
    const float* b2  = (const float*)d_in[8];
    float* out = (float*)d_out;

    int N = in_sizes[0] / 128;
    int E = in_sizes[2];

    int nb = (N + 511) / 512;
    int gb = (N + 31) / 32;
    int ab = (N + 7) / 8;

    // gemm1 kept at launch index 3 (ncu capture window). Deps preserved on stream 0.
    dz_kernel<<<(N * RR + 255) / 256, 256>>>(ei, et, E, N, N * RR, N);      // 0
    count_kernel<<<(E + 255) / 256, 256>>>(ei, et, E, N);                    // 1
    scan1_kernel<<<nb, 512>>>(N);                                            // 2
    gemm_kernel<128, 1><<<gb, 128>>>(x, W1r, W1o, b1, nullptr, N);           // 3
    scan2_kernel<<<1, 512>>>(nb);                                            // 4
    fill_kernel<<<(E + 255) / 256, 256>>>(ei, et, E, N);                     // 5
    agg_kernel<1><<<ab, 256>>>(nullptr, N);                                  // 6
    gemm_kernel<64, 2><<<gb, 128>>>(nullptr, W2r, W2o, b2, out, N);          // 7
    agg_kernel<2><<<ab, 256>>>(out, N);                                      // 8
}